// round 10
// baseline (speedup 1.0000x reference)
#include <cuda_runtime.h>
#include <cuda_fp16.h>
#include <cstdint>

// W8A16 linear, single-pass fp16 mma.sync (compute_103-safe).
// out[M,N] = (x[M,K] @ W[N,K]^T) * scales[N] + bias[N]
//   Prequant: W int8-in-int32 -> fp16 (exact); x fp32 -> fp16 (rel err 2^-11).
//   GEMM: CTA 128x256, 512 threads, 16 warps = 4(m)x4(n), warp tile 32x64,
//   BK=64, cp.async 3-stage pipeline, ldmatrix non-trans fragments,
//   mma.sync.m16n8k16.f32.f16.f16.f32.
//   Rationale: 16-warp CTA halves smem bytes/MAC (88 vs 128 per 1M MACs)
//   while keeping 16 warps/SM for latency hiding.

#define GK 4096
#define GM 4096
#define GN 11008

__device__ __half g_xh[(size_t)GM * GK];
__device__ __half g_wh[(size_t)GN * GK];

// ---------------- helpers ----------------
__device__ __forceinline__ uint32_t s2u(const void* p) {
    uint32_t a;
    asm("{ .reg .u64 t; cvta.to.shared.u64 t, %1; cvt.u32.u64 %0, t; }" : "=r"(a) : "l"(p));
    return a;
}
#define CP_ASYNC16(dst, src) \
    asm volatile("cp.async.cg.shared.global [%0], [%1], 16;" :: "r"(dst), "l"(src))
#define CP_COMMIT() asm volatile("cp.async.commit_group;" ::: "memory")
#define CP_WAIT(n)  asm volatile("cp.async.wait_group %0;" :: "n"(n) : "memory")

#define LDSM_X4(r0, r1, r2, r3, a)                                              \
    asm volatile("ldmatrix.sync.aligned.m8n8.x4.shared.b16 {%0,%1,%2,%3}, [%4];" \
                 : "=r"(r0), "=r"(r1), "=r"(r2), "=r"(r3) : "r"(a))

// ---------------- prequant ----------------
__global__ void wprequant_kernel(const int* __restrict__ w, int n4) {
    int stride = gridDim.x * blockDim.x;
    for (int i = blockIdx.x * blockDim.x + threadIdx.x; i < n4; i += stride) {
        int4 v = reinterpret_cast<const int4*>(w)[i];
        __half2 p0 = __floats2half2_rn((float)v.x, (float)v.y);   // exact
        __half2 p1 = __floats2half2_rn((float)v.z, (float)v.w);
        uint2 pk;
        pk.x = *reinterpret_cast<uint32_t*>(&p0);
        pk.y = *reinterpret_cast<uint32_t*>(&p1);
        reinterpret_cast<uint2*>(g_wh)[i] = pk;
    }
}

__global__ void xprequant_kernel(const float* __restrict__ x, int n4) {
    int stride = gridDim.x * blockDim.x;
    for (int i = blockIdx.x * blockDim.x + threadIdx.x; i < n4; i += stride) {
        float4 v = reinterpret_cast<const float4*>(x)[i];
        __half2 p0 = __floats2half2_rn(v.x, v.y);
        __half2 p1 = __floats2half2_rn(v.z, v.w);
        uint2 pk;
        pk.x = *reinterpret_cast<uint32_t*>(&p0);
        pk.y = *reinterpret_cast<uint32_t*>(&p1);
        reinterpret_cast<uint2*>(g_xh)[i] = pk;
    }
}

// ---------------- GEMM ----------------
#define BM 128
#define BN 256
#define BK 64
#define NTHR 512
#define ATILE 16384                 // 128 rows x 128 B
#define BTILE 32768                 // 256 rows x 128 B
#define STAGEB (ATILE + BTILE)      // 49152
#define NSTAGE 3
#define SMEMB  (NSTAGE * STAGEB)    // 147456
#define SWZ_G  16                   // M-group size for grid swizzle

__global__ __launch_bounds__(NTHR, 1)
void w8a16_hmma_kernel(const float* __restrict__ scales,
                       const float* __restrict__ bias,
                       float* __restrict__ out,
                       int M, int N, int K)
{
    extern __shared__ char sm[];
    const uint32_t sb = s2u(sm);
    const int tid  = threadIdx.x;
    const int lane = tid & 31;
    const int warp = tid >> 5;
    const int wm = warp >> 2;            // 0..3 -> m offset 32*wm
    const int wn = warp & 3;             // 0..3 -> n offset 64*wn

    // ---- grid swizzle: concurrent CTAs cover a 16(M) x ~9(N) patch ----
    const int lb  = blockIdx.y * gridDim.x + blockIdx.x;
    const int tps = SWZ_G * gridDim.x;          // tiles per stripe
    const int stripe = lb / tps;
    const int rem    = lb - stripe * tps;
    const int xg = rem / SWZ_G;                 // N tile index
    const int yg = stripe * SWZ_G + (rem - xg * SWZ_G);  // M tile index

    const int mbase = yg * BM;
    const int nbase = xg * BN;

    const __half* ag  = g_xh + (size_t)mbase * K;
    const __half* bgp = g_wh + (size_t)nbase * K;

    float acc[2][8][4];
    #pragma unroll
    for (int mi = 0; mi < 2; ++mi)
        #pragma unroll
        for (int ni = 0; ni < 8; ++ni)
            #pragma unroll
            for (int c = 0; c < 4; ++c)
                acc[mi][ni][c] = 0.0f;

    // ldmatrix lane address components (non-trans x4 for both operands)
    const int a_rl = (lane & 7) + ((lane >> 3) & 1) * 8;   // row within m16
    const int a_cb = lane >> 4;                            // k8-chunk select
    const int b_rl = (lane & 7) + ((lane >> 4) << 3);      // row within n16
    const int b_cb = (lane >> 3) & 1;

    const int ar0 = wm * 32 + a_rl;            // mi=0 row
    const int ar1 = ar0 + 16;                  // mi=1 row
    const uint32_t arow0 = (uint32_t)ar0 * 128, am0 = (uint32_t)(ar0 & 7);
    const uint32_t arow1 = (uint32_t)ar1 * 128, am1 = (uint32_t)(ar1 & 7);

    uint32_t brow[4], bm7[4];
    #pragma unroll
    for (int nj = 0; nj < 4; ++nj) {
        int r = wn * 64 + nj * 16 + b_rl;
        brow[nj] = (uint32_t)r * 128;
        bm7[nj]  = (uint32_t)(r & 7);
    }

    const int nch = K / BK;                    // 64

    // issue one stage: A 1024 + B 2048 = 3072 x 16B chunks, 6 per thread
    #define ISSUE_STAGE(st, k0) do {                                             \
        uint32_t dstb = sb + (st) * STAGEB;                                      \
        _Pragma("unroll")                                                        \
        for (int cc = 0; cc < 6; ++cc) {                                         \
            int cid  = tid + cc * NTHR;         /* 0..3071 */                    \
            int isB  = cid >= 1024;                                              \
            int rem2 = isB ? (cid - 1024) : cid;                                 \
            int row  = rem2 >> 3;                                                \
            int c    = rem2 & 7;                                                 \
            const __half* src = (isB ? bgp : ag) + (size_t)row * K + (k0) + c * 8; \
            uint32_t dst = dstb + (isB ? ATILE : 0) + row * 128 +                \
                           ((uint32_t)(c ^ (row & 7)) << 4);                     \
            CP_ASYNC16(dst, src);                                                \
        }                                                                        \
        CP_COMMIT();                                                             \
    } while (0)

    ISSUE_STAGE(0, 0);
    ISSUE_STAGE(1, BK);

    int stage = 0;
    for (int i = 0; i < nch; ++i) {
        if (i + 1 < nch) { CP_WAIT(1); } else { CP_WAIT(0); }
        __syncthreads();
        if (i + 2 < nch) {
            int st2 = stage + 2;
            if (st2 >= NSTAGE) st2 -= NSTAGE;
            ISSUE_STAGE(st2, (i + 2) * BK);
        }

        const uint32_t as = sb + stage * STAGEB;
        const uint32_t bs = as + ATILE;

        #pragma unroll
        for (int ks = 0; ks < 4; ++ks) {
            const uint32_t kc2 = (uint32_t)(ks * 2);

            uint32_t bf[4][4];
            #pragma unroll
            for (int nj = 0; nj < 4; ++nj) {
                uint32_t addr = bs + brow[nj] + (((kc2 + b_cb) ^ bm7[nj]) << 4);
                LDSM_X4(bf[nj][0], bf[nj][1], bf[nj][2], bf[nj][3], addr);
            }

            uint32_t af0[4], af1[4];
            {
                uint32_t addr = as + arow0 + (((kc2 + a_cb) ^ am0) << 4);
                LDSM_X4(af0[0], af0[1], af0[2], af0[3], addr);
                addr = as + arow1 + (((kc2 + a_cb) ^ am1) << 4);
                LDSM_X4(af1[0], af1[1], af1[2], af1[3], addr);
            }

            #pragma unroll
            for (int nj = 0; nj < 4; ++nj) {
                #pragma unroll
                for (int h = 0; h < 2; ++h) {       // ni = nj*2 + h
                    const int ni = nj * 2 + h;
                    asm volatile(
                        "mma.sync.aligned.m16n8k16.row.col.f32.f16.f16.f32 "
                        "{%0,%1,%2,%3}, {%4,%5,%6,%7}, {%8,%9}, {%0,%1,%2,%3};\n"
                        : "+f"(acc[0][ni][0]), "+f"(acc[0][ni][1]),
                          "+f"(acc[0][ni][2]), "+f"(acc[0][ni][3])
                        : "r"(af0[0]), "r"(af0[1]), "r"(af0[2]), "r"(af0[3]),
                          "r"(bf[nj][h * 2]), "r"(bf[nj][h * 2 + 1]));
                    asm volatile(
                        "mma.sync.aligned.m16n8k16.row.col.f32.f16.f16.f32 "
                        "{%0,%1,%2,%3}, {%4,%5,%6,%7}, {%8,%9}, {%0,%1,%2,%3};\n"
                        : "+f"(acc[1][ni][0]), "+f"(acc[1][ni][1]),
                          "+f"(acc[1][ni][2]), "+f"(acc[1][ni][3])
                        : "r"(af1[0]), "r"(af1[1]), "r"(af1[2]), "r"(af1[3]),
                          "r"(bf[nj][h * 2]), "r"(bf[nj][h * 2 + 1]));
                }
            }
        }

        if (++stage == NSTAGE) stage = 0;
    }

    // ---- epilogue: y = acc * scales[n] + bias[n] ----
    #pragma unroll
    for (int mi = 0; mi < 2; ++mi) {
        const int r0 = mbase + wm * 32 + mi * 16 + (lane >> 2);
        float* o0 = out + (size_t)r0 * N + nbase;
        float* o1 = out + (size_t)(r0 + 8) * N + nbase;
        #pragma unroll
        for (int ni = 0; ni < 8; ++ni) {
            const int gn = wn * 64 + ni * 8 + ((lane & 3) << 1);
            const float s0 = scales[nbase + gn], s1 = scales[nbase + gn + 1];
            const float b0 = bias[nbase + gn],   b1 = bias[nbase + gn + 1];
            float2 v;
            v.x = acc[mi][ni][0] * s0 + b0;
            v.y = acc[mi][ni][1] * s1 + b1;
            *reinterpret_cast<float2*>(o0 + gn) = v;
            v.x = acc[mi][ni][2] * s0 + b0;
            v.y = acc[mi][ni][3] * s1 + b1;
            *reinterpret_cast<float2*>(o1 + gn) = v;
        }
    }
}

extern "C" void kernel_launch(void* const* d_in, const int* in_sizes, int n_in,
                              void* d_out, int out_size)
{
    const float* x      = (const float*) d_in[0];
    const int*   w      = (const int*)   d_in[1];   // int8 values in int32 storage
    const float* scales = (const float*) d_in[2];
    const float* bias   = (const float*) d_in[3];
    float*       out    = (float*)       d_out;

    const int N = in_sizes[2];            // 11008
    const int K = in_sizes[1] / N;        // 4096
    const int M = in_sizes[0] / K;        // 4096

    cudaFuncSetAttribute(w8a16_hmma_kernel,
                         cudaFuncAttributeMaxDynamicSharedMemorySize, SMEMB);

    wprequant_kernel<<<2048, 256>>>(w, (N * K) / 4);
    xprequant_kernel<<<2048, 256>>>(x, (M * K) / 4);
    dim3 grid(N / BN, M / BM);            // 43 x 32
    w8a16_hmma_kernel<<<grid, NTHR, SMEMB>>>(scales, bias, out, M, N, K);
}

// round 11
// speedup vs baseline: 1.1323x; 1.1323x over previous
#include <cuda_runtime.h>
#include <cuda_fp16.h>
#include <cstdint>

// W8A16 linear, single-pass fp16 mma.sync (compute_103-safe).
// out[M,N] = (x[M,K] @ W[N,K]^T) * scales[N] + bias[N]
//   Prequant: W int8-in-int32 -> fp16 (exact); x fp32 -> fp16 (rel err 2^-11).
//   GEMM: 1 CTA x 256 thr, tile 128x256, warp tile 64x64 (low smem traffic:
//   176KB/2.1M MACs vs 256KB for 128x128-pair), BK=64, 4-stage cp.async
//   pipeline synchronized with mbarriers (no __syncthreads convoy):
//     full[s]: count 256, completed via cp.async.mbarrier.arrive.noinc
//     empty[s]: count 8, release-arrive per warp after its LDSM reads

#define GK 4096
#define GM 4096
#define GN 11008

__device__ __half g_xh[(size_t)GM * GK];
__device__ __half g_wh[(size_t)GN * GK];

// ---------------- helpers ----------------
__device__ __forceinline__ uint32_t s2u(const void* p) {
    uint32_t a;
    asm("{ .reg .u64 t; cvta.to.shared.u64 t, %1; cvt.u32.u64 %0, t; }" : "=r"(a) : "l"(p));
    return a;
}
#define CP_ASYNC16(dst, src) \
    asm volatile("cp.async.cg.shared.global [%0], [%1], 16;" :: "r"(dst), "l"(src))

#define LDSM_X4(r0, r1, r2, r3, a)                                              \
    asm volatile("ldmatrix.sync.aligned.m8n8.x4.shared.b16 {%0,%1,%2,%3}, [%4];" \
                 : "=r"(r0), "=r"(r1), "=r"(r2), "=r"(r3) : "r"(a))

#define MBARRIER_INIT(mb, c) \
    asm volatile("mbarrier.init.shared.b64 [%0], %1;" :: "r"((uint32_t)(mb)), "r"((uint32_t)(c)) : "memory")
#define MBARRIER_ARRIVE(mb) \
    asm volatile("mbarrier.arrive.shared.b64 _, [%0];" :: "r"((uint32_t)(mb)) : "memory")
#define CPASYNC_MBAR_ARRIVE(mb) \
    asm volatile("cp.async.mbarrier.arrive.noinc.shared::cta.b64 [%0];" :: "r"((uint32_t)(mb)) : "memory")

#define MBARRIER_WAIT_PARITY(mb, par) do {                                          \
    uint32_t _mb = (uint32_t)(mb); uint32_t _p = (uint32_t)(par); uint32_t _done;   \
    asm volatile("{\n\t.reg .pred p;\n\t"                                           \
        "mbarrier.try_wait.parity.acquire.cta.shared::cta.b64 p, [%1], %2;\n\t"     \
        "selp.b32 %0, 1, 0, p;\n\t}"                                                \
        : "=r"(_done) : "r"(_mb), "r"(_p) : "memory");                              \
    if (!_done) {                                                                   \
        asm volatile("{\n\t.reg .pred P1;\n\t"                                      \
            "WL_%=:\n\t"                                                            \
            "mbarrier.try_wait.parity.acquire.cta.shared::cta.b64 P1, [%0], %1, 0x989680;\n\t" \
            "@P1 bra.uni WD_%=;\n\t"                                                \
            "bra.uni WL_%=;\n\t"                                                    \
            "WD_%=:\n\t}"                                                           \
            :: "r"(_mb), "r"(_p) : "memory");                                       \
    }                                                                               \
} while (0)

// ---------------- prequant ----------------
__global__ void wprequant_kernel(const int* __restrict__ w, int n4) {
    int stride = gridDim.x * blockDim.x;
    for (int i = blockIdx.x * blockDim.x + threadIdx.x; i < n4; i += stride) {
        int4 v = reinterpret_cast<const int4*>(w)[i];
        __half2 p0 = __floats2half2_rn((float)v.x, (float)v.y);   // exact
        __half2 p1 = __floats2half2_rn((float)v.z, (float)v.w);
        uint2 pk;
        pk.x = *reinterpret_cast<uint32_t*>(&p0);
        pk.y = *reinterpret_cast<uint32_t*>(&p1);
        reinterpret_cast<uint2*>(g_wh)[i] = pk;
    }
}

__global__ void xprequant_kernel(const float* __restrict__ x, int n4) {
    int stride = gridDim.x * blockDim.x;
    for (int i = blockIdx.x * blockDim.x + threadIdx.x; i < n4; i += stride) {
        float4 v = reinterpret_cast<const float4*>(x)[i];
        __half2 p0 = __floats2half2_rn(v.x, v.y);
        __half2 p1 = __floats2half2_rn(v.z, v.w);
        uint2 pk;
        pk.x = *reinterpret_cast<uint32_t*>(&p0);
        pk.y = *reinterpret_cast<uint32_t*>(&p1);
        reinterpret_cast<uint2*>(g_xh)[i] = pk;
    }
}

// ---------------- GEMM ----------------
#define BM 128
#define BN 256
#define BK 64
#define NTHR 256
#define ATILE 16384                 // 128 rows x 128 B
#define BTILE 32768                 // 256 rows x 128 B
#define STAGEB (ATILE + BTILE)      // 49152
#define NSTAGE 4
#define STAGES_B (NSTAGE * STAGEB)  // 196608
#define SMEMB (STAGES_B + 128)      // + mbarriers
#define SWZ_G 8                     // M-group size for grid swizzle

__global__ __launch_bounds__(NTHR, 1)
void w8a16_hmma_kernel(const float* __restrict__ scales,
                       const float* __restrict__ bias,
                       float* __restrict__ out,
                       int M, int N, int K)
{
    extern __shared__ char sm[];
    const uint32_t sb = s2u(sm);
    const uint32_t mb_full  = sb + STAGES_B;        // 4 x 8B
    const uint32_t mb_empty = sb + STAGES_B + 32;   // 4 x 8B
    const int tid  = threadIdx.x;
    const int lane = tid & 31;
    const int warp = tid >> 5;
    const int wm = warp >> 2;            // 0..1 -> m offset 64*wm
    const int wn = warp & 3;             // 0..3 -> n offset 64*wn

    // ---- grid swizzle ----
    const int lb  = blockIdx.y * gridDim.x + blockIdx.x;
    const int tps = SWZ_G * gridDim.x;
    const int stripe = lb / tps;
    const int rem    = lb - stripe * tps;
    const int xg = rem / SWZ_G;
    const int yg = stripe * SWZ_G + (rem - xg * SWZ_G);

    const int mbase = yg * BM;
    const int nbase = xg * BN;

    const __half* ag  = g_xh + (size_t)mbase * K;
    const __half* bgp = g_wh + (size_t)nbase * K;

    // ---- mbarrier init ----
    if (tid == 0) {
        #pragma unroll
        for (int s = 0; s < NSTAGE; ++s) {
            MBARRIER_INIT(mb_full  + s * 8, NTHR);  // all threads' cp.async arrivals
            MBARRIER_INIT(mb_empty + s * 8, 8);     // one arrive per warp
        }
    }
    __syncthreads();

    float acc[4][8][4];
    #pragma unroll
    for (int mi = 0; mi < 4; ++mi)
        #pragma unroll
        for (int ni = 0; ni < 8; ++ni)
            #pragma unroll
            for (int c = 0; c < 4; ++c)
                acc[mi][ni][c] = 0.0f;

    // ldmatrix lane address components (non-trans x4 for both operands)
    const int a_rl = (lane & 7) + ((lane >> 3) & 1) * 8;   // row within m16
    const int a_cb = lane >> 4;                            // k8-chunk select
    const int b_rl = (lane & 7) + ((lane >> 4) << 3);      // row within n16
    const int b_cb = (lane >> 3) & 1;

    uint32_t arow[4], am7[4];
    #pragma unroll
    for (int mi = 0; mi < 4; ++mi) {
        int r = wm * 64 + mi * 16 + a_rl;
        arow[mi] = (uint32_t)r * 128;
        am7[mi]  = (uint32_t)(r & 7);
    }
    uint32_t brow[4], bm7[4];
    #pragma unroll
    for (int nj = 0; nj < 4; ++nj) {
        int r = wn * 64 + nj * 16 + b_rl;
        brow[nj] = (uint32_t)r * 128;
        bm7[nj]  = (uint32_t)(r & 7);
    }

    const int nch = K / BK;                    // 64

    // issue one stage: A 1024 + B 2048 = 3072 x 16B chunks, 12 per thread,
    // then bind this thread's copies to the stage's full barrier.
    #define ISSUE_STAGE(st, k0) do {                                             \
        uint32_t dstb = sb + (st) * STAGEB;                                      \
        _Pragma("unroll")                                                        \
        for (int cc = 0; cc < 12; ++cc) {                                        \
            int cid  = tid + cc * NTHR;         /* 0..3071 */                    \
            int isB  = cid >= 1024;                                              \
            int rem2 = isB ? (cid - 1024) : cid;                                 \
            int row  = rem2 >> 3;                                                \
            int c    = rem2 & 7;                                                 \
            const __half* src = (isB ? bgp : ag) + (size_t)row * K + (k0) + c * 8; \
            uint32_t dst = dstb + (isB ? ATILE : 0) + row * 128 +                \
                           ((uint32_t)(c ^ (row & 7)) << 4);                     \
            CP_ASYNC16(dst, src);                                                \
        }                                                                        \
        CPASYNC_MBAR_ARRIVE(mb_full + (st) * 8);                                 \
    } while (0)

    // prologue: fill all 4 stages
    ISSUE_STAGE(0, 0);
    ISSUE_STAGE(1, BK);
    ISSUE_STAGE(2, 2 * BK);
    ISSUE_STAGE(3, 3 * BK);

    for (int i = 0; i < nch; ++i) {
        const int s = i & 3;
        const int q = i >> 2;

        MBARRIER_WAIT_PARITY(mb_full + s * 8, q & 1);

        const uint32_t as = sb + s * STAGEB;
        const uint32_t bs = as + ATILE;

        #pragma unroll
        for (int ks = 0; ks < 4; ++ks) {
            const uint32_t kc2 = (uint32_t)(ks * 2);

            uint32_t bf[4][4];
            #pragma unroll
            for (int nj = 0; nj < 4; ++nj) {
                uint32_t addr = bs + brow[nj] + (((kc2 + b_cb) ^ bm7[nj]) << 4);
                LDSM_X4(bf[nj][0], bf[nj][1], bf[nj][2], bf[nj][3], addr);
            }

            uint32_t af[4][4];
            #pragma unroll
            for (int mi = 0; mi < 4; ++mi) {
                uint32_t addr = as + arow[mi] + (((kc2 + a_cb) ^ am7[mi]) << 4);
                LDSM_X4(af[mi][0], af[mi][1], af[mi][2], af[mi][3], addr);
            }

            #pragma unroll
            for (int mi = 0; mi < 4; ++mi) {
                #pragma unroll
                for (int nj = 0; nj < 4; ++nj) {
                    #pragma unroll
                    for (int h = 0; h < 2; ++h) {       // ni = nj*2 + h
                        const int ni = nj * 2 + h;
                        asm volatile(
                            "mma.sync.aligned.m16n8k16.row.col.f32.f16.f16.f32 "
                            "{%0,%1,%2,%3}, {%4,%5,%6,%7}, {%8,%9}, {%0,%1,%2,%3};\n"
                            : "+f"(acc[mi][ni][0]), "+f"(acc[mi][ni][1]),
                              "+f"(acc[mi][ni][2]), "+f"(acc[mi][ni][3])
                            : "r"(af[mi][0]), "r"(af[mi][1]),
                              "r"(af[mi][2]), "r"(af[mi][3]),
                              "r"(bf[nj][h * 2]), "r"(bf[nj][h * 2 + 1]));
                    }
                }
            }
        }

        // this warp is done reading stage s (ldmatrix is warp-synchronous)
        if (lane == 0) MBARRIER_ARRIVE(mb_empty + s * 8);

        // refill stage s for chunk i+4 once ALL warps have consumed chunk i
        const int j = i + 4;
        if (j < nch) {
            MBARRIER_WAIT_PARITY(mb_empty + s * 8, q & 1);
            ISSUE_STAGE(s, j * BK);
        }
    }

    // ---- epilogue: y = acc * scales[n] + bias[n] ----
    #pragma unroll
    for (int mi = 0; mi < 4; ++mi) {
        const int r0 = mbase + wm * 64 + mi * 16 + (lane >> 2);
        float* o0 = out + (size_t)r0 * N + nbase;
        float* o1 = out + (size_t)(r0 + 8) * N + nbase;
        #pragma unroll
        for (int ni = 0; ni < 8; ++ni) {
            const int gn = wn * 64 + ni * 8 + ((lane & 3) << 1);
            const float s0 = scales[nbase + gn], s1 = scales[nbase + gn + 1];
            const float b0 = bias[nbase + gn],   b1 = bias[nbase + gn + 1];
            float2 v;
            v.x = acc[mi][ni][0] * s0 + b0;
            v.y = acc[mi][ni][1] * s1 + b1;
            *reinterpret_cast<float2*>(o0 + gn) = v;
            v.x = acc[mi][ni][2] * s0 + b0;
            v.y = acc[mi][ni][3] * s1 + b1;
            *reinterpret_cast<float2*>(o1 + gn) = v;
        }
    }
}

extern "C" void kernel_launch(void* const* d_in, const int* in_sizes, int n_in,
                              void* d_out, int out_size)
{
    const float* x      = (const float*) d_in[0];
    const int*   w      = (const int*)   d_in[1];   // int8 values in int32 storage
    const float* scales = (const float*) d_in[2];
    const float* bias   = (const float*) d_in[3];
    float*       out    = (float*)       d_out;

    const int N = in_sizes[2];            // 11008
    const int K = in_sizes[1] / N;        // 4096
    const int M = in_sizes[0] / K;        // 4096

    cudaFuncSetAttribute(w8a16_hmma_kernel,
                         cudaFuncAttributeMaxDynamicSharedMemorySize, SMEMB);

    wprequant_kernel<<<2048, 256>>>(w, (N * K) / 4);
    xprequant_kernel<<<2048, 256>>>(x, (M * K) / 4);
    dim3 grid(N / BN, M / BM);            // 43 x 32
    w8a16_hmma_kernel<<<grid, NTHR, SMEMB>>>(scales, bias, out, M, N, K);
}